// round 9
// baseline (speedup 1.0000x reference)
#include <cuda_runtime.h>

// Problem constants
#define Bn   4
#define Hq   512
#define Wq   512
#define Cn   128
#define Hon  502
#define Won  502
#define OFFS 2
// Tiling: block (8,4,9); tile 4 rows x 64 cols; tz == dy; 8 px per thread
#define TH   4
#define TW   64
#define NTX  8
#define NTZ  9
#define NTHR 288
#define CCK  8
#define NCHUNK 16
#define QR   12            // TH + 8 halo rows
#define QW   72            // TW + 8 halo cols
#define QPAD 76
#define PPAD 68

#define TILE_FLOATS (QR*CCK*QPAD + TH*CCK*PPAD)   // 7296 + 2176 = 9472
#define SMEM_BYTES  (2 * TILE_FLOATS * 4)          // 75776 (out staging 10368 floats fits)

// Packed fp32x2 helpers (sm_103a)
#define FMA2(d, a, b) asm("fma.rn.f32x2 %0, %1, %2, %0;" : "+l"(d) : "l"(a), "l"(b))
#define PACK2(r, lo, hi) asm("mov.b64 %0, {%1, %2};" : "=l"(r) : "f"(lo), "f"(hi))
#define UNPACK2(lo, hi, r) asm("mov.b64 {%0, %1}, %2;" : "=f"(lo), "=f"(hi) : "l"(r))

__global__ __launch_bounds__(NTHR, 1)
void corr9x9_db_kernel(const float* __restrict__ pg,
                       const float* __restrict__ qg,
                       float* __restrict__ outg)
{
    extern __shared__ __align__(16) float smem[];

    const int tx  = threadIdx.x;             // 0..7
    const int ty  = threadIdx.y;             // 0..3
    const int tz  = threadIdx.z;             // 0..8 == dy
    const int tid = tx + NTX * (ty + TH * tz);

    const int wo0 = blockIdx.x * TW;
    const int ho0 = blockIdx.y * TH;
    const int b   = blockIdx.z;

    const float* pb = pg + (size_t)b * Hon * Won * Cn;
    const float* qb = qg + (size_t)b * Hq  * Wq  * Cn;

    // ---- precompute staging offsets ----
    int qoff[6], qdst[6];
    #pragma unroll
    for (int i = 0; i < 6; ++i) {
        int flat = tid + i * NTHR;          // exactly covers QR*QW*2 = 1728
        int c4   = flat & 1;
        int t    = flat >> 1;
        int w    = t % QW;
        int rr   = t / QW;
        int hr   = ho0 + OFFS + rr; if (hr > Hq - 1) hr = Hq - 1;
        int wr   = wo0 + OFFS + w;  if (wr > Wq - 1) wr = Wq - 1;
        qoff[i]  = (hr * Wq + wr) * Cn + c4 * 4;
        qdst[i]  = (rr * CCK + c4 * 4) * QPAD + w;
    }
    int poff[2], pdst[2];
    bool pok[2];
    #pragma unroll
    for (int i = 0; i < 2; ++i) {
        int flat = tid + i * NTHR;
        pok[i]  = (flat < TH * TW * 2);      // 512
        int f   = pok[i] ? flat : 0;
        int c4  = f & 1;
        int t   = f >> 1;
        int w   = t & (TW - 1);
        int rw  = t >> 6;
        int hr  = ho0 + rw; if (hr > Hon - 1) hr = Hon - 1;
        int wr  = wo0 + w;  if (wr > Won - 1) wr = Won - 1;
        poff[i] = (hr * Won + wr) * Cn + c4 * 4;
        pdst[i] = (rw * CCK + c4 * 4) * PPAD + w;
    }

    // ---- accumulators: 4 pixel-pairs x 9 dx, packed f32x2 ----
    unsigned long long acc[4][9];
    #pragma unroll
    for (int j = 0; j < 4; ++j)
        #pragma unroll
        for (int dx = 0; dx < 9; ++dx)
            acc[j][dx] = 0ull;

    const int r  = ty + tz;                  // q tile row for this thread
    const int w0 = tx * 8;                   // first pixel of this thread

    float4 qpf[6], ppf[2];

    // ---- prolog: LDG chunk0, STS chunk0 -> buf0, LDG chunk1 ----
    #pragma unroll
    for (int i = 0; i < 6; ++i)
        qpf[i] = *(const float4*)(qb + qoff[i]);
    #pragma unroll
    for (int i = 0; i < 2; ++i)
        if (pok[i]) ppf[i] = *(const float4*)(pb + poff[i]);

    {
        float* q_s = smem;
        float* p_s = smem + QR * CCK * QPAD;
        #pragma unroll
        for (int i = 0; i < 6; ++i) {
            q_s[qdst[i]           ] = qpf[i].x;
            q_s[qdst[i] +     QPAD] = qpf[i].y;
            q_s[qdst[i] + 2 * QPAD] = qpf[i].z;
            q_s[qdst[i] + 3 * QPAD] = qpf[i].w;
        }
        #pragma unroll
        for (int i = 0; i < 2; ++i) {
            if (pok[i]) {
                p_s[pdst[i]           ] = ppf[i].x;
                p_s[pdst[i] +     PPAD] = ppf[i].y;
                p_s[pdst[i] + 2 * PPAD] = ppf[i].z;
                p_s[pdst[i] + 3 * PPAD] = ppf[i].w;
            }
        }
    }
    #pragma unroll
    for (int i = 0; i < 6; ++i)
        qpf[i] = *(const float4*)(qb + qoff[i] + CCK);
    #pragma unroll
    for (int i = 0; i < 2; ++i)
        if (pok[i]) ppf[i] = *(const float4*)(pb + poff[i] + CCK);
    __syncthreads();

    // ---- main ping-pong loop: one barrier per chunk ----
    for (int k = 0; k < NCHUNK; ++k) {
        const float* q_s = smem + (k & 1) * TILE_FLOATS;
        const float* p_s = q_s + QR * CCK * QPAD;

        // compute chunk k
        #pragma unroll
        for (int c = 0; c < CCK; ++c) {
            const float* qrow = q_s + (r * CCK + c) * QPAD + w0;
            const float* prow = p_s + (ty * CCK + c) * PPAD + w0;

            const float4 pv0 = *(const float4*)(prow);
            const float4 pv1 = *(const float4*)(prow + 4);
            unsigned long long pp[4];
            PACK2(pp[0], pv0.x, pv0.y);
            PACK2(pp[1], pv0.z, pv0.w);
            PACK2(pp[2], pv1.x, pv1.y);
            PACK2(pp[3], pv1.z, pv1.w);

            const float4 a0 = *(const float4*)(qrow);
            const float4 a1 = *(const float4*)(qrow + 4);
            const float4 a2 = *(const float4*)(qrow + 8);
            const float4 a3 = *(const float4*)(qrow + 12);
            float qf[16] = {a0.x, a0.y, a0.z, a0.w,
                            a1.x, a1.y, a1.z, a1.w,
                            a2.x, a2.y, a2.z, a2.w,
                            a3.x, a3.y, a3.z, a3.w};
            unsigned long long pr[15];
            #pragma unroll
            for (int j = 0; j < 15; ++j)
                PACK2(pr[j], qf[j], qf[j + 1]);

            #pragma unroll
            for (int j = 0; j < 4; ++j)
                #pragma unroll
                for (int dx = 0; dx < 9; ++dx)
                    FMA2(acc[j][dx], pp[j], pr[2 * j + dx]);
        }

        if (k + 1 < NCHUNK) {
            // STS chunk k+1 into the other buffer (its old readers finished
            // at the barrier that ended iteration k-1)
            float* q_d = smem + ((k + 1) & 1) * TILE_FLOATS;
            float* p_d = q_d + QR * CCK * QPAD;
            #pragma unroll
            for (int i = 0; i < 6; ++i) {
                q_d[qdst[i]           ] = qpf[i].x;
                q_d[qdst[i] +     QPAD] = qpf[i].y;
                q_d[qdst[i] + 2 * QPAD] = qpf[i].z;
                q_d[qdst[i] + 3 * QPAD] = qpf[i].w;
            }
            #pragma unroll
            for (int i = 0; i < 2; ++i) {
                if (pok[i]) {
                    p_d[pdst[i]           ] = ppf[i].x;
                    p_d[pdst[i] +     PPAD] = ppf[i].y;
                    p_d[pdst[i] + 2 * PPAD] = ppf[i].z;
                    p_d[pdst[i] + 3 * PPAD] = ppf[i].w;
                }
            }
            // LDG chunk k+2 (lands during compute of chunk k+1)
            if (k + 2 < NCHUNK) {
                int cc = (k + 2) * CCK;
                #pragma unroll
                for (int i = 0; i < 6; ++i)
                    qpf[i] = *(const float4*)(qb + qoff[i] + cc);
                #pragma unroll
                for (int i = 0; i < 2; ++i)
                    if (pok[i]) ppf[i] = *(const float4*)(pb + poff[i] + cc);
            }
            __syncthreads();
        }
    }

    // ---- epilogue: smem-staged coalesced output, 2 slabs of 2 rows ----
    float* out_s = smem;    // [2][TW][81] = 10368 floats (barrier below protects)
    #pragma unroll
    for (int s = 0; s < 2; ++s) {
        __syncthreads();
        if ((ty >> 1) == s) {
            const int rr = ty & 1;
            #pragma unroll
            for (int j = 0; j < 4; ++j) {
                float* d0 = out_s + (rr * TW + w0 + 2 * j) * 81 + tz * 9;
                float* d1 = d0 + 81;
                #pragma unroll
                for (int dx = 0; dx < 9; ++dx) {
                    float lo, hi;
                    UNPACK2(lo, hi, acc[j][dx]);
                    d0[dx] = lo;
                    d1[dx] = hi;
                }
            }
        }
        __syncthreads();
        // cooperative coalesced copy: 10368 floats, 36 per thread
        #pragma unroll
        for (int kk = 0; kk < 36; ++kk) {
            int f   = tid + kk * NTHR;
            int rr  = f / (TW * 81);
            int rem = f - rr * (TW * 81);
            int px  = rem / 81;
            int ho  = ho0 + 2 * s + rr;
            if (ho < Hon && (wo0 + px) < Won) {
                size_t dst = ((size_t)(b * Hon + ho) * Won + wo0) * 81 + rem;
                __stcs(&outg[dst], out_s[f]);
            }
        }
    }
}

extern "C" void kernel_launch(void* const* d_in, const int* in_sizes, int n_in,
                              void* d_out, int out_size)
{
    const float* p = (const float*)d_in[0];
    const float* q = (const float*)d_in[1];
    float* out = (float*)d_out;

    cudaFuncSetAttribute(corr9x9_db_kernel,
                         cudaFuncAttributeMaxDynamicSharedMemorySize, SMEM_BYTES);

    dim3 block(NTX, TH, NTZ);                  // 8 x 4 x 9 = 288
    dim3 grid((Won + TW - 1) / TW,             // 8
              (Hon + TH - 1) / TH,             // 126
              Bn);                             // 4
    corr9x9_db_kernel<<<grid, block, SMEM_BYTES>>>(p, q, out);
}

// round 10
// speedup vs baseline: 1.1718x; 1.1718x over previous
#include <cuda_runtime.h>

// Problem constants
#define Bn   4
#define Hq   512
#define Wq   512
#define Cn   128
#define Hon  502
#define Won  502
#define OFFS 2
// Tiling: block (8,4,9); tile 4 rows x 64 cols; tz == dy; 2 groups of 4 px
#define TH   4
#define TW   64
#define NTX  8
#define NTZ  9
#define NTHR 288
#define CCK  8
#define NCHUNK 16
#define QR   12            // TH + 8 halo rows
#define QW   72            // TW + 8 halo cols
#define QPAD 76
#define PPAD 68

#define TILE_FLOATS (QR*CCK*QPAD + TH*CCK*PPAD)   // 7296 + 2176 = 9472
#define SMEM_BYTES  (2 * TILE_FLOATS * 4)          // 75776; out staging 10368 floats fits

// Packed fp32x2 helpers (sm_103a)
#define FMA2(d, a, b) asm("fma.rn.f32x2 %0, %1, %2, %0;" : "+l"(d) : "l"(a), "l"(b))
#define PACK2(r, lo, hi) asm("mov.b64 %0, {%1, %2};" : "=l"(r) : "f"(lo), "f"(hi))
#define UNPACK2(lo, hi, r) asm("mov.b64 {%0, %1}, %2;" : "=f"(lo), "=f"(hi) : "l"(r))

__global__ __launch_bounds__(NTHR, 1)
void corr9x9_db2_kernel(const float* __restrict__ pg,
                        const float* __restrict__ qg,
                        float* __restrict__ outg)
{
    extern __shared__ __align__(16) float smem[];

    const int tx  = threadIdx.x;             // 0..7
    const int ty  = threadIdx.y;             // 0..3
    const int tz  = threadIdx.z;             // 0..8 == dy
    const int tid = tx + NTX * (ty + TH * tz);

    const int wo0 = blockIdx.x * TW;
    const int ho0 = blockIdx.y * TH;
    const int b   = blockIdx.z;

    const float* pb = pg + (size_t)b * Hon * Won * Cn;
    const float* qb = qg + (size_t)b * Hq  * Wq  * Cn;

    // ---- precompute staging offsets ----
    int qoff[6], qdst[6];
    #pragma unroll
    for (int i = 0; i < 6; ++i) {
        int flat = tid + i * NTHR;          // exactly covers QR*QW*2 = 1728
        int c4   = flat & 1;
        int t    = flat >> 1;
        int w    = t % QW;
        int rr   = t / QW;
        int hr   = ho0 + OFFS + rr; if (hr > Hq - 1) hr = Hq - 1;
        int wr   = wo0 + OFFS + w;  if (wr > Wq - 1) wr = Wq - 1;
        qoff[i]  = (hr * Wq + wr) * Cn + c4 * 4;
        qdst[i]  = (rr * CCK + c4 * 4) * QPAD + w;
    }
    int poff[2], pdst[2];
    bool pok[2];
    #pragma unroll
    for (int i = 0; i < 2; ++i) {
        int flat = tid + i * NTHR;
        pok[i]  = (flat < TH * TW * 2);      // 512
        int f   = pok[i] ? flat : 0;
        int c4  = f & 1;
        int t   = f >> 1;
        int w   = t & (TW - 1);
        int rw  = t >> 6;
        int hr  = ho0 + rw; if (hr > Hon - 1) hr = Hon - 1;
        int wr  = wo0 + w;  if (wr > Won - 1) wr = Won - 1;
        poff[i] = (hr * Won + wr) * Cn + c4 * 4;
        pdst[i] = (rw * CCK + c4 * 4) * PPAD + w;
    }

    // ---- accumulators: [group][pair][dx], packed f32x2 ----
    unsigned long long acc[2][2][9];
    #pragma unroll
    for (int g = 0; g < 2; ++g)
        #pragma unroll
        for (int j = 0; j < 2; ++j)
            #pragma unroll
            for (int dx = 0; dx < 9; ++dx)
                acc[g][j][dx] = 0ull;

    const int r = ty + tz;                   // q tile row for this thread

    float4 qpf[6], ppf[2];

    // ---- prolog: LDG chunk0, STS chunk0 -> buf0, LDG chunk1 ----
    #pragma unroll
    for (int i = 0; i < 6; ++i)
        qpf[i] = *(const float4*)(qb + qoff[i]);
    #pragma unroll
    for (int i = 0; i < 2; ++i)
        if (pok[i]) ppf[i] = *(const float4*)(pb + poff[i]);

    {
        float* q_s = smem;
        float* p_s = smem + QR * CCK * QPAD;
        #pragma unroll
        for (int i = 0; i < 6; ++i) {
            q_s[qdst[i]           ] = qpf[i].x;
            q_s[qdst[i] +     QPAD] = qpf[i].y;
            q_s[qdst[i] + 2 * QPAD] = qpf[i].z;
            q_s[qdst[i] + 3 * QPAD] = qpf[i].w;
        }
        #pragma unroll
        for (int i = 0; i < 2; ++i) {
            if (pok[i]) {
                p_s[pdst[i]           ] = ppf[i].x;
                p_s[pdst[i] +     PPAD] = ppf[i].y;
                p_s[pdst[i] + 2 * PPAD] = ppf[i].z;
                p_s[pdst[i] + 3 * PPAD] = ppf[i].w;
            }
        }
    }
    #pragma unroll
    for (int i = 0; i < 6; ++i)
        qpf[i] = *(const float4*)(qb + qoff[i] + CCK);
    #pragma unroll
    for (int i = 0; i < 2; ++i)
        if (pok[i]) ppf[i] = *(const float4*)(pb + poff[i] + CCK);
    __syncthreads();

    // ---- main ping-pong loop: one barrier per chunk ----
    for (int k = 0; k < NCHUNK; ++k) {
        const float* q_s = smem + (k & 1) * TILE_FLOATS;
        const float* p_s = q_s + QR * CCK * QPAD;

        // compute chunk k — two groups of 4 px, stride-4 lanes (conflict-free)
        #pragma unroll
        for (int c = 0; c < CCK; ++c) {
            const float* qrow = q_s + (r * CCK + c) * QPAD;
            const float* prow = p_s + (ty * CCK + c) * PPAD;
            #pragma unroll
            for (int g = 0; g < 2; ++g) {
                const int w0 = g * 32 + tx * 4;
                const float4 pv = *(const float4*)(prow + w0);
                unsigned long long pp[2];
                PACK2(pp[0], pv.x, pv.y);
                PACK2(pp[1], pv.z, pv.w);

                const float4 a0 = *(const float4*)(qrow + w0);
                const float4 a1 = *(const float4*)(qrow + w0 + 4);
                const float4 a2 = *(const float4*)(qrow + w0 + 8);
                float qf[12] = {a0.x, a0.y, a0.z, a0.w,
                                a1.x, a1.y, a1.z, a1.w,
                                a2.x, a2.y, a2.z, a2.w};
                unsigned long long pr[11];
                #pragma unroll
                for (int j = 0; j < 11; ++j)
                    PACK2(pr[j], qf[j], qf[j + 1]);

                #pragma unroll
                for (int dx = 0; dx < 9; ++dx) {
                    FMA2(acc[g][0][dx], pp[0], pr[dx]);
                    FMA2(acc[g][1][dx], pp[1], pr[dx + 2]);
                }
            }
        }

        if (k + 1 < NCHUNK) {
            // STS chunk k+1 into the other buffer (its readers finished at
            // the barrier that ended iteration k-1)
            float* q_d = smem + ((k + 1) & 1) * TILE_FLOATS;
            float* p_d = q_d + QR * CCK * QPAD;
            #pragma unroll
            for (int i = 0; i < 6; ++i) {
                q_d[qdst[i]           ] = qpf[i].x;
                q_d[qdst[i] +     QPAD] = qpf[i].y;
                q_d[qdst[i] + 2 * QPAD] = qpf[i].z;
                q_d[qdst[i] + 3 * QPAD] = qpf[i].w;
            }
            #pragma unroll
            for (int i = 0; i < 2; ++i) {
                if (pok[i]) {
                    p_d[pdst[i]           ] = ppf[i].x;
                    p_d[pdst[i] +     PPAD] = ppf[i].y;
                    p_d[pdst[i] + 2 * PPAD] = ppf[i].z;
                    p_d[pdst[i] + 3 * PPAD] = ppf[i].w;
                }
            }
            // LDG chunk k+2 (lands during compute of chunk k+1)
            if (k + 2 < NCHUNK) {
                int cc = (k + 2) * CCK;
                #pragma unroll
                for (int i = 0; i < 6; ++i)
                    qpf[i] = *(const float4*)(qb + qoff[i] + cc);
                #pragma unroll
                for (int i = 0; i < 2; ++i)
                    if (pok[i]) ppf[i] = *(const float4*)(pb + poff[i] + cc);
            }
            __syncthreads();
        }
    }

    // ---- epilogue: smem-staged coalesced output, 2 slabs of 2 rows ----
    float* out_s = smem;    // [2][TW][81] = 10368 floats
    #pragma unroll
    for (int s = 0; s < 2; ++s) {
        __syncthreads();
        if ((ty >> 1) == s) {
            const int rr = ty & 1;
            #pragma unroll
            for (int g = 0; g < 2; ++g) {
                const int w0 = g * 32 + tx * 4;
                #pragma unroll
                for (int j = 0; j < 2; ++j) {
                    float* d0 = out_s + (rr * TW + w0 + 2 * j) * 81 + tz * 9;
                    float* d1 = d0 + 81;
                    #pragma unroll
                    for (int dx = 0; dx < 9; ++dx) {
                        float lo, hi;
                        UNPACK2(lo, hi, acc[g][j][dx]);
                        d0[dx] = lo;
                        d1[dx] = hi;
                    }
                }
            }
        }
        __syncthreads();
        // cooperative coalesced copy: 10368 floats, 36 per thread
        #pragma unroll
        for (int kk = 0; kk < 36; ++kk) {
            int f   = tid + kk * NTHR;
            int rr  = f / (TW * 81);
            int rem = f - rr * (TW * 81);
            int px  = rem / 81;
            int ho  = ho0 + 2 * s + rr;
            if (ho < Hon && (wo0 + px) < Won) {
                size_t dst = ((size_t)(b * Hon + ho) * Won + wo0) * 81 + rem;
                __stcs(&outg[dst], out_s[f]);
            }
        }
    }
}

extern "C" void kernel_launch(void* const* d_in, const int* in_sizes, int n_in,
                              void* d_out, int out_size)
{
    const float* p = (const float*)d_in[0];
    const float* q = (const float*)d_in[1];
    float* out = (float*)d_out;

    cudaFuncSetAttribute(corr9x9_db2_kernel,
                         cudaFuncAttributeMaxDynamicSharedMemorySize, SMEM_BYTES);

    dim3 block(NTX, TH, NTZ);                  // 8 x 4 x 9 = 288
    dim3 grid((Won + TW - 1) / TW,             // 8
              (Hon + TH - 1) / TH,             // 126
              Bn);                             // 4
    corr9x9_db2_kernel<<<grid, block, SMEM_BYTES>>>(p, q, out);
}

// round 11
// speedup vs baseline: 1.3886x; 1.1850x over previous
#include <cuda_runtime.h>

// Problem constants
#define Bn   4
#define Hq   512
#define Wq   512
#define Cn   128
#define Hon  502
#define Won  502
#define OFFS 2
// Tiling: block (16,4,9) = 576 threads; tile 4 rows x 64 cols; tz == dy; 4 px/thread
#define TH   4
#define TW   64
#define NTX  16
#define NTY  4
#define NTZ  9
#define NTHR 576
#define CCK  16
#define NCHUNK 8
#define QR   12            // TH + 8 halo rows
#define QW   72            // TW + 8 halo cols
#define QPAD 76
#define PPAD 68

#define QS_FLOATS   (QR*CCK*QPAD)              // 14592
#define PS_FLOATS   (TH*CCK*PPAD)              // 4352
#define TILE_FLOATS (QS_FLOATS + PS_FLOATS)    // 18944
#define SMEM_BYTES  (2 * TILE_FLOATS * 4)      // 151552

// Packed fp32x2 helpers (sm_103a)
#define FMA2(d, a, b) asm("fma.rn.f32x2 %0, %1, %2, %0;" : "+l"(d) : "l"(a), "l"(b))
#define PACK2(r, lo, hi) asm("mov.b64 %0, {%1, %2};" : "=l"(r) : "f"(lo), "f"(hi))
#define UNPACK2(lo, hi, r) asm("mov.b64 {%0, %1}, %2;" : "=f"(lo), "=f"(hi) : "l"(r))

__global__ __launch_bounds__(NTHR, 1)
void corr9x9_w18_kernel(const float* __restrict__ pg,
                        const float* __restrict__ qg,
                        float* __restrict__ outg)
{
    extern __shared__ __align__(16) float smem[];

    const int tx  = threadIdx.x;             // 0..15
    const int ty  = threadIdx.y;             // 0..3
    const int tz  = threadIdx.z;             // 0..8 == dy
    const int tid = tx + NTX * (ty + NTY * tz);

    const int wo0 = blockIdx.x * TW;
    const int ho0 = blockIdx.y * TH;
    const int b   = blockIdx.z;

    const float* pb = pg + (size_t)b * Hon * Won * Cn;
    const float* qb = qg + (size_t)b * Hq  * Wq  * Cn;

    // ---- staging assignments ----
    // q: 6 float4 per thread per chunk (covers QR*QW*4 = 3456 float4 exactly).
    // 4 consecutive lanes (c4=0..3) read 64B contiguous gmem.
    // Channel c4*4+k lands in smem channel-row rho = 2*c4 + (k&1) + 8*(k>>1):
    //   .x -> 2c4, .y -> 2c4+1, .z -> 2c4+8, .w -> 2c4+9  (STS conflict-free)
    int qoff[6], qdst[6];
    #pragma unroll
    for (int i = 0; i < 6; ++i) {
        int flat = tid + i * NTHR;
        int c4   = flat & 3;
        int t    = flat >> 2;                // 0..863
        int w    = t % QW;
        int rr   = t / QW;                   // 0..11
        int hr   = ho0 + OFFS + rr; if (hr > Hq - 1) hr = Hq - 1;
        int wr   = wo0 + OFFS + w;  if (wr > Wq - 1) wr = Wq - 1;
        qoff[i]  = (hr * Wq + wr) * Cn + c4 * 4;
        qdst[i]  = (rr * CCK + 2 * c4) * QPAD + w;
    }
    // p: 2 float4 per thread, mask (covers TH*TW*4 = 1024 float4)
    int poff[2], pdst[2];
    bool pok[2];
    #pragma unroll
    for (int i = 0; i < 2; ++i) {
        int flat = tid + i * NTHR;
        pok[i]  = (flat < TH * TW * 4);
        int f   = pok[i] ? flat : 0;
        int c4  = f & 3;
        int t   = f >> 2;
        int w   = t & (TW - 1);
        int rw  = t >> 6;
        int hr  = ho0 + rw; if (hr > Hon - 1) hr = Hon - 1;
        int wr  = wo0 + w;  if (wr > Won - 1) wr = Won - 1;
        poff[i] = (hr * Won + wr) * Cn + c4 * 4;
        pdst[i] = (rw * CCK + 2 * c4) * PPAD + w;
    }

    // ---- accumulators: 2 pixel-pairs x 9 dx ----
    unsigned long long acc[2][9];
    #pragma unroll
    for (int j = 0; j < 2; ++j)
        #pragma unroll
        for (int dx = 0; dx < 9; ++dx)
            acc[j][dx] = 0ull;

    const int r  = ty + tz;                  // q pixel row (0..11)
    const int w0 = tx * 4;                   // first pixel (stride-4 lanes: conflict-free)

    float4 qpf[6], ppf[2];

    // ---- prolog: LDG chunk0, STS -> buf0, LDG chunk1 ----
    #pragma unroll
    for (int i = 0; i < 6; ++i) qpf[i] = *(const float4*)(qb + qoff[i]);
    #pragma unroll
    for (int i = 0; i < 2; ++i) if (pok[i]) ppf[i] = *(const float4*)(pb + poff[i]);
    {
        float* q_s = smem;
        float* p_s = smem + QS_FLOATS;
        #pragma unroll
        for (int i = 0; i < 6; ++i) {
            q_s[qdst[i]           ] = qpf[i].x;
            q_s[qdst[i] +     QPAD] = qpf[i].y;
            q_s[qdst[i] + 8 * QPAD] = qpf[i].z;
            q_s[qdst[i] + 9 * QPAD] = qpf[i].w;
        }
        #pragma unroll
        for (int i = 0; i < 2; ++i) {
            if (pok[i]) {
                p_s[pdst[i]           ] = ppf[i].x;
                p_s[pdst[i] +     PPAD] = ppf[i].y;
                p_s[pdst[i] + 8 * PPAD] = ppf[i].z;
                p_s[pdst[i] + 9 * PPAD] = ppf[i].w;
            }
        }
    }
    #pragma unroll
    for (int i = 0; i < 6; ++i) qpf[i] = *(const float4*)(qb + qoff[i] + CCK);
    #pragma unroll
    for (int i = 0; i < 2; ++i) if (pok[i]) ppf[i] = *(const float4*)(pb + poff[i] + CCK);
    __syncthreads();

    // ---- main ping-pong loop: one barrier per chunk ----
    for (int k = 0; k < NCHUNK; ++k) {
        const float* q_s = smem + (k & 1) * TILE_FLOATS;
        const float* p_s = q_s + QS_FLOATS;

        #pragma unroll
        for (int c = 0; c < CCK; ++c) {
            const float* qrow = q_s + (r  * CCK + c) * QPAD + w0;
            const float* prow = p_s + (ty * CCK + c) * PPAD + w0;

            const float4 pv = *(const float4*)(prow);
            unsigned long long pp0, pp1;
            PACK2(pp0, pv.x, pv.y);
            PACK2(pp1, pv.z, pv.w);

            const float4 a0 = *(const float4*)(qrow);
            const float4 a1 = *(const float4*)(qrow + 4);
            const float4 a2 = *(const float4*)(qrow + 8);
            float qf[12] = {a0.x, a0.y, a0.z, a0.w,
                            a1.x, a1.y, a1.z, a1.w,
                            a2.x, a2.y, a2.z, a2.w};

            // rolling pair window: pr[j] feeds acc[0][j] and acc[1][j-2]
            #pragma unroll
            for (int j = 0; j < 11; ++j) {
                unsigned long long pr;
                PACK2(pr, qf[j], qf[j + 1]);
                if (j < 9)  FMA2(acc[0][j],     pp0, pr);
                if (j >= 2) FMA2(acc[1][j - 2], pp1, pr);
            }
        }

        if (k + 1 < NCHUNK) {
            float* q_d = smem + ((k + 1) & 1) * TILE_FLOATS;
            float* p_d = q_d + QS_FLOATS;
            #pragma unroll
            for (int i = 0; i < 6; ++i) {
                q_d[qdst[i]           ] = qpf[i].x;
                q_d[qdst[i] +     QPAD] = qpf[i].y;
                q_d[qdst[i] + 8 * QPAD] = qpf[i].z;
                q_d[qdst[i] + 9 * QPAD] = qpf[i].w;
            }
            #pragma unroll
            for (int i = 0; i < 2; ++i) {
                if (pok[i]) {
                    p_d[pdst[i]           ] = ppf[i].x;
                    p_d[pdst[i] +     PPAD] = ppf[i].y;
                    p_d[pdst[i] + 8 * PPAD] = ppf[i].z;
                    p_d[pdst[i] + 9 * PPAD] = ppf[i].w;
                }
            }
            if (k + 2 < NCHUNK) {
                int cc = (k + 2) * CCK;
                #pragma unroll
                for (int i = 0; i < 6; ++i)
                    qpf[i] = *(const float4*)(qb + qoff[i] + cc);
                #pragma unroll
                for (int i = 0; i < 2; ++i)
                    if (pok[i]) ppf[i] = *(const float4*)(pb + poff[i] + cc);
            }
            __syncthreads();
        }
    }

    // ---- epilogue: smem-staged coalesced output, 2 slabs of 2 rows ----
    float* out_s = smem;    // [2][TW][81] = 10368 floats
    #pragma unroll
    for (int s = 0; s < 2; ++s) {
        __syncthreads();
        if ((ty >> 1) == s) {
            const int rr_ = ty & 1;
            #pragma unroll
            for (int j = 0; j < 2; ++j) {
                float* d0 = out_s + (rr_ * TW + w0 + 2 * j) * 81 + tz * 9;
                float* d1 = d0 + 81;
                #pragma unroll
                for (int dx = 0; dx < 9; ++dx) {
                    float lo, hi;
                    UNPACK2(lo, hi, acc[j][dx]);
                    d0[dx] = lo;
                    d1[dx] = hi;
                }
            }
        }
        __syncthreads();
        // cooperative coalesced copy: 10368 floats, 18 per thread
        #pragma unroll
        for (int kk = 0; kk < 18; ++kk) {
            int f   = tid + kk * NTHR;
            int rr_ = f / (TW * 81);
            int rem = f - rr_ * (TW * 81);
            int px  = rem / 81;
            int ho  = ho0 + 2 * s + rr_;
            if (ho < Hon && (wo0 + px) < Won) {
                size_t dst = ((size_t)(b * Hon + ho) * Won + wo0) * 81 + rem;
                __stcs(&outg[dst], out_s[f]);
            }
        }
    }
}

extern "C" void kernel_launch(void* const* d_in, const int* in_sizes, int n_in,
                              void* d_out, int out_size)
{
    const float* p = (const float*)d_in[0];
    const float* q = (const float*)d_in[1];
    float* out = (float*)d_out;

    cudaFuncSetAttribute(corr9x9_w18_kernel,
                         cudaFuncAttributeMaxDynamicSharedMemorySize, SMEM_BYTES);

    dim3 block(NTX, NTY, NTZ);                 // 16 x 4 x 9 = 576
    dim3 grid((Won + TW - 1) / TW,             // 8
              (Hon + TH - 1) / TH,             // 126
              Bn);                             // 4
    corr9x9_w18_kernel<<<grid, block, SMEM_BYTES>>>(p, q, out);
}